// round 17
// baseline (speedup 1.0000x reference)
#include <cuda_runtime.h>
#include <cstdint>

// Problem constants
#define Bx 256
#define Tx 3000
#define Ix 40
#define Hx 64
#define Gx 256        // 4*H gates
#define RCH 8         // recurrent chunk steps (3000 % 8 == 0 -> 375 chunks)

// Scratch (allocation-free rule: __device__ globals)
__device__ float g_h[2][(size_t)Bx * Tx * Hx];    // per-direction hidden outputs

// ---------- packed f32x2 helpers ----------
union F2U { float2 f; unsigned long long u; };

__device__ __forceinline__ void ffma2(unsigned long long& acc,
                                      unsigned long long a,
                                      unsigned long long b) {
    asm("fma.rn.f32x2 %0, %1, %2, %0;" : "+l"(acc) : "l"(a), "l"(b));
}
__device__ __forceinline__ unsigned long long fadd2(unsigned long long a, unsigned long long b) {
    unsigned long long r;
    asm("add.rn.f32x2 %0, %1, %2;" : "=l"(r) : "l"(a), "l"(b));
    return r;
}
__device__ __forceinline__ float fsigmoid(float x) {
    return __fdividef(1.0f, 1.0f + __expf(-x));
}
__device__ __forceinline__ float ftanh_fast(float x) {
    return 1.0f - __fdividef(2.0f, __expf(2.0f * x) + 1.0f);
}
__device__ __forceinline__ float hsum2(unsigned long long a, unsigned long long b) {
    F2U s; s.u = fadd2(a, b);
    return s.f.x + s.f.y;
}

// ---------- cp.async helpers ----------
__device__ __forceinline__ unsigned int smem_u32(const void* p) {
    return (unsigned int)__cvta_generic_to_shared(p);
}
__device__ __forceinline__ void cp_async16(unsigned int s, const void* g) {
    asm volatile("cp.async.cg.shared.global [%0], [%1], 16;" :: "r"(s), "l"(g));
}
#define CP_COMMIT() asm volatile("cp.async.commit_group;")
#define CP_WAIT1()  asm volatile("cp.async.wait_group 1;")

// ================= fused LSTM kernel (chunk-bulk input projection) =================
// R13-exact recurrence structure (2 seqs/block, 256 blocks, 2 blocks/SM,
// sgates exchange, 2 barriers/step, phase-2 guard). NEW: the separate xproj
// kernel is deleted; at each chunk top a bulk burst computes the chunk's
// 16 x-projections (8 steps x 2 seqs) per thread with short independent
// chains, writing column g of sxp which only thread g reads (no extra sync).
// cp.async stages raw x (1.25KB/chunk/seq) instead of 8KB of xp.
__global__ __launch_bounds__(256, 2)
void lstm_kernel(const float* __restrict__ x,
                 const float* __restrict__ WihF, const float* __restrict__ WhhF,
                 const float* __restrict__ bihF, const float* __restrict__ bhhF,
                 const float* __restrict__ WihB, const float* __restrict__ WhhB,
                 const float* __restrict__ bihB, const float* __restrict__ bhhB)
{
    const int dir   = blockIdx.x & 1;
    const int bpair = blockIdx.x >> 1;          // 0..127
    const int bA    = 2 * bpair;

    const float* Whh = dir ? WhhB : WhhF;
    const float* Wih = dir ? WihB : WihF;
    float* hout = g_h[dir];

    const int g = threadIdx.x;
    const int region = g >> 6;                  // warp-uniform gate type (2 = tanh)
    const int us  = (g >> 6) & 1;               // phase-2 seq (g < 128)
    const int uix = g & 63;                     // phase-2 h index

    __shared__ __align__(16) float sxp[2][RCH * Gx];     // [seq] 16 KB (single buffer)
    __shared__ __align__(16) float sx[2][2][RCH * Ix];   // [seq][buf] x chunks, 5 KB
    __shared__ __align__(16) float sh[2][Hx];
    __shared__ float sgates[2][Gx];

    // W_hh row (64 floats = 32 u64) + W_ih row (40 floats = 20 u64) in regs
    unsigned long long whh[32], wih[20];
    {
        const float2* wr = (const float2*)(Whh + (size_t)g * Hx);
        #pragma unroll
        for (int j = 0; j < 32; j++) { F2U a; a.f = wr[j]; whh[j] = a.u; }
        const float2* wi = (const float2*)(Wih + (size_t)g * Ix);
        #pragma unroll
        for (int j = 0; j < 20; j++) { F2U a; a.f = wi[j]; wih[j] = a.u; }
    }
    const float bias = dir ? (bihB[g] + bhhB[g]) : (bihF[g] + bhhF[g]);

    if (g < 128) sh[g >> 6][g & 63] = 0.0f;
    float c = 0.0f;

    // x staging: chunk = RCH steps x 40 floats = 1280B per seq = 80 x 16B.
    // threads 0..159: seq = tid/80, 16B segment (tid%80)*16.  (R11-proven)
    const int  cth  = (threadIdx.x < 160);
    const int  cseq = cth ? (threadIdx.x / 80) : 0;
    const int  coff = (threadIdx.x % 80) * 16;
    const char* xbase = (const char*)(x + (size_t)(bA + cseq) * Tx * Ix) + coff;
    const unsigned int sb0 = smem_u32(&sx[cseq][0][0]) + coff;
    const unsigned int sb1 = smem_u32(&sx[cseq][1][0]) + coff;
    const int ROWB = Ix * 4;                    // 160 bytes per timestep

    // phase-2 output pointer (g<128)
    float* hptr = hout + ((size_t)(bA + us) * Tx + (dir ? (Tx - 1) : 0)) * Hx + uix;
    const ptrdiff_t hstep = dir ? -Hx : Hx;

    // chunk ck's lowest timestep (staged rows are t = tlo .. tlo+RCH-1)
    auto tlo = [&](int ck) { return dir ? (Tx - RCH - ck * RCH) : (ck * RCH); };

    // prefetch chunk 0 into buffer 0
    if (cth) cp_async16(sb0, xbase + (size_t)tlo(0) * ROWB);
    CP_COMMIT();
    __syncthreads();   // sh init visible (and keeps group counting uniform)

    const int NCH = Tx / RCH;
    for (int ck = 0; ck < NCH; ck++) {
        // prefetch ck+1; commit; wait for ck; barrier (R3/R13-proven pattern)
        if (ck + 1 < NCH) {
            if (cth) {
                const unsigned int sdst = ((ck + 1) & 1) ? sb1 : sb0;
                cp_async16(sdst, xbase + (size_t)tlo(ck + 1) * ROWB);
            }
        }
        CP_COMMIT();
        CP_WAIT1();
        __syncthreads();

        const int cb = ck & 1;

        // ---- bulk x-projection burst for this chunk (self-column, no sync) ----
        // burst slot si holds the projection for step index si of this chunk:
        //   dir=0: staged row si  (t = tlo+si   = srel)
        //   dir=1: staged row 7-si (t = tlo+7-si = Tx-1-srel)
        #pragma unroll
        for (int si = 0; si < RCH; si++) {
            const int row = dir ? (RCH - 1 - si) : si;
            const ulonglong2* xrA = (const ulonglong2*)(&sx[0][cb][row * Ix]);
            const ulonglong2* xrB = (const ulonglong2*)(&sx[1][cb][row * Ix]);
            F2U aA0, aA1, aB0, aB1;
            aA0.f = make_float2(bias, 0.0f);
            aB0 = aA0;
            aA1.f = make_float2(0.0f, 0.0f);
            aB1 = aA1;
            #pragma unroll
            for (int j = 0; j < 10; j++) {
                const ulonglong2 ua = xrA[j];   // broadcast LDS.128
                const ulonglong2 ub = xrB[j];
                ffma2(aA0.u, ua.x, wih[2 * j]);
                ffma2(aA1.u, ua.y, wih[2 * j + 1]);
                ffma2(aB0.u, ub.x, wih[2 * j]);
                ffma2(aB1.u, ub.y, wih[2 * j + 1]);
            }
            sxp[0][si * Gx + g] = hsum2(aA0.u, aA1.u);
            sxp[1][si * Gx + g] = hsum2(aB0.u, aB1.u);
        }

        // ---- steps: BYTE-IDENTICAL to R13 body, xv from sxp ----
        #pragma unroll 1
        for (int si = 0; si < RCH; si++) {
            const float xvA = sxp[0][si * Gx + g];
            const float xvB = sxp[1][si * Gx + g];

            F2U aA0, aA1, aB0, aB1;
            aA0.f = make_float2(xvA, 0.0f);
            aB0.f = make_float2(xvB, 0.0f);
            aA1.f = make_float2(0.0f, 0.0f);
            aB1 = aA1;

            const ulonglong2* hA = (const ulonglong2*)sh[0];  // LDS.128 broadcast
            const ulonglong2* hB = (const ulonglong2*)sh[1];
            #pragma unroll
            for (int j = 0; j < 16; j++) {
                const ulonglong2 ua = hA[j];
                const ulonglong2 ub = hB[j];
                ffma2(aA0.u, ua.x, whh[2 * j]);
                ffma2(aA1.u, ua.y, whh[2 * j + 1]);
                ffma2(aB0.u, ub.x, whh[2 * j]);
                ffma2(aB1.u, ub.y, whh[2 * j + 1]);
            }
            const float vA = hsum2(aA0.u, aA1.u);
            const float vB = hsum2(aB0.u, aB1.u);

            if (region == 2) {
                sgates[0][g] = ftanh_fast(vA);
                sgates[1][g] = ftanh_fast(vB);
            } else {
                sgates[0][g] = fsigmoid(vA);
                sgates[1][g] = fsigmoid(vB);
            }
            __syncthreads();

            if (g < 128) {
                const float ig = sgates[us][uix];
                const float fg = sgates[us][64 + uix];
                const float gg = sgates[us][128 + uix];
                const float og = sgates[us][192 + uix];
                c = fg * c + ig * gg;
                const float h = og * ftanh_fast(c);
                sh[us][uix] = h;
                *hptr = h;
                hptr += hstep;
            }
            __syncthreads();
        }
    }
}

// ================= MLP head kernel (R1-exact, measured 567us) =================
__global__ __launch_bounds__(256, 1)
void head_kernel(const float* __restrict__ W1, const float* __restrict__ b1,
                 const float* __restrict__ W2, const float* __restrict__ b2,
                 float* __restrict__ out)
{
    __shared__ __align__(16) float sW1[64 * 128];  // 32 KB
    __shared__ float sb1[64];
    __shared__ float sW2[64];
    __shared__ float sb2;

    const int tid = threadIdx.x;
    for (int i = tid; i < 64 * 128; i += 256) sW1[i] = W1[i];
    if (tid < 64) { sb1[tid] = b1[tid]; sW2[tid] = W2[tid]; }
    if (tid == 0) sb2 = b2[0];
    __syncthreads();

    const size_t tok = (size_t)blockIdx.x * 256 + tid;

    unsigned long long hreg[64];
    {
        const float2* pf = (const float2*)(g_h[0] + tok * Hx);
        const float2* pb = (const float2*)(g_h[1] + tok * Hx);
        #pragma unroll
        for (int j = 0; j < 32; j++) { F2U u; u.f = pf[j]; hreg[j] = u.u; }
        #pragma unroll
        for (int j = 0; j < 32; j++) { F2U u; u.f = pb[j]; hreg[32 + j] = u.u; }
    }

    float acc_out = sb2;
    for (int o = 0; o < 64; o++) {
        F2U a0, a1, a2, a3;
        a0.f = make_float2(sb1[o], 0.0f);
        a1.f = make_float2(0.0f, 0.0f);
        a2.f = a1.f; a3.f = a1.f;
        const ulonglong2* w = (const ulonglong2*)(sW1 + o * 128);  // 16B LDS, broadcast
        #pragma unroll
        for (int j = 0; j < 16; j++) {
            const ulonglong2 wv0 = w[2 * j];
            const ulonglong2 wv1 = w[2 * j + 1];
            ffma2(a0.u, hreg[4 * j + 0], wv0.x);
            ffma2(a1.u, hreg[4 * j + 1], wv0.y);
            ffma2(a2.u, hreg[4 * j + 2], wv1.x);
            ffma2(a3.u, hreg[4 * j + 3], wv1.y);
        }
        float z = (a0.f.x + a0.f.y) + (a1.f.x + a1.f.y)
                + (a2.f.x + a2.f.y) + (a3.f.x + a3.f.y);
        z = fmaxf(z, 0.0f);
        acc_out = fmaf(z, sW2[o], acc_out);
    }
    out[tok] = fsigmoid(acc_out);
}

// ================= launch =================
extern "C" void kernel_launch(void* const* d_in, const int* in_sizes, int n_in,
                              void* d_out, int out_size)
{
    const float* x     = (const float*)d_in[0];
    const float* Wih_f = (const float*)d_in[1];
    const float* Whh_f = (const float*)d_in[2];
    const float* bih_f = (const float*)d_in[3];
    const float* bhh_f = (const float*)d_in[4];
    const float* Wih_b = (const float*)d_in[5];
    const float* Whh_b = (const float*)d_in[6];
    const float* bih_b = (const float*)d_in[7];
    const float* bhh_b = (const float*)d_in[8];
    const float* W1    = (const float*)d_in[9];
    const float* b1    = (const float*)d_in[10];
    const float* W2    = (const float*)d_in[11];
    const float* b2    = (const float*)d_in[12];
    float* out = (float*)d_out;

    lstm_kernel<<<Bx, 256>>>(x, Wih_f, Whh_f, bih_f, bhh_f,
                             Wih_b, Whh_b, bih_b, bhh_b);
    head_kernel<<<(Bx * Tx) / 256, 256>>>(W1, b1, W2, b2, out);
}